// round 3
// baseline (speedup 1.0000x reference)
#include <cuda_runtime.h>

#define NA    100000
#define NEDGE 200000
#define HID   512
#define AD    133
#define BD    14
#define KIN   147   // AD + BD
#define KOUT  645   // AD + HID

// ---------------- scratch (static device globals; no allocation) ------------
__device__ float g_h0 [(size_t)NEDGE * HID];
__device__ float g_hA [(size_t)NEDGE * HID];
__device__ float g_hB [(size_t)NEDGE * HID];
__device__ float g_agg[(size_t)NA    * HID];

// ---------------- utility kernels ------------------------------------------
__global__ void zero_k(float4* __restrict__ p, int n4) {
    int i = blockIdx.x * blockDim.x + threadIdx.x;
    if (i < n4) p[i] = make_float4(0.f, 0.f, 0.f, 0.f);
}

// agg[dst[e]] += w[e] * h[e]   (weighted; wgt==nullptr -> w=1)
__global__ void scatter_k(const float* __restrict__ h,
                          const int* __restrict__ dst,
                          const float* __restrict__ wgt,
                          float* __restrict__ agg) {
    int idx = blockIdx.x * blockDim.x + threadIdx.x;      // NEDGE * 128 threads
    if (idx >= NEDGE * 128) return;
    int e = idx >> 7;
    int c = (idx & 127) << 2;
    int d = dst[e];
    float w = wgt ? wgt[e] : 1.0f;
    float4 hv = *(const float4*)(h + (size_t)e * HID + c);
    float* a = agg + (size_t)d * HID + c;
    atomicAdd(a + 0, w * hv.x);
    atomicAdd(a + 1, w * hv.y);
    atomicAdd(a + 2, w * hv.z);
    atomicAdd(a + 3, w * hv.w);
}

__global__ void batch_k(const int* __restrict__ b, float* __restrict__ out) {
    int i = blockIdx.x * blockDim.x + threadIdx.x;
    if (i < NA) out[i] = (float)b[i];
}

__global__ void copy4_k(const float4* __restrict__ src, float4* __restrict__ dst, int n4) {
    int i = blockIdx.x * blockDim.x + threadIdx.x;
    if (i < n4) dst[i] = src[i];
}

// ---------------- fused SGEMM -----------------------------------------------
// C[M,512] = relu( A @ W^T (+ add) )
// MODE 1: A row e = [V[src[e]] ; E[e]]                          K=147
// MODE 2: A row e = agg[src[e]] - wgt[rev[e]] * Hin[rev[e]]     K=512, add=h0[row]
// MODE 3: A row i = [V[i] ; agg[i]]                             K=645, add=bias[col]
template <int MODE>
__global__ __launch_bounds__(256)
void gemm_k(const float* __restrict__ Hin,
            const float* __restrict__ W,
            const float* __restrict__ Vf,
            const float* __restrict__ Eb,
            const int* __restrict__ src,
            const int* __restrict__ rev,
            const float* __restrict__ wgt,
            const float* __restrict__ agg,
            const float* __restrict__ h0,
            const float* __restrict__ bias,
            float* __restrict__ C,
            int M, int K)
{
    __shared__ __align__(16) float As[8][132];
    __shared__ __align__(16) float Bs[8][128];

    const int tid   = threadIdx.x;
    const int row_l = tid >> 1;            // 0..127 (A row within tile, also B col)
    const int k_l   = (tid & 1) * 4;       // 0 or 4
    const int grow  = blockIdx.x * 128 + row_l;
    const int jb    = blockIdx.y * 128;
    const bool rowok = (grow < M);

    // per-row gather metadata (constant across K loop)
    int   sidx = 0, ridx = 0;
    float wr   = 0.f;
    if (MODE == 1) { if (rowok) sidx = src[grow]; }
    if (MODE == 2) { if (rowok) { sidx = src[grow]; ridx = rev[grow]; wr = wgt[ridx]; } }

    const int tm0 = (tid >> 4) * 8;
    const int tn0 = (tid & 15) * 8;

    float acc[8][8];
#pragma unroll
    for (int i = 0; i < 8; i++)
#pragma unroll
        for (int j = 0; j < 8; j++) acc[i][j] = 0.f;

    for (int kb = 0; kb < K; kb += 8) {
        // ---- A tile (fused gather / message formation) ----
        float a[4];
        if (MODE == 2) {
            if (rowok) {
                float4 ag = *(const float4*)(agg + (size_t)sidx * HID + kb + k_l);
                float4 hh = *(const float4*)(Hin + (size_t)ridx * HID + kb + k_l);
                a[0] = ag.x - wr * hh.x;  a[1] = ag.y - wr * hh.y;
                a[2] = ag.z - wr * hh.z;  a[3] = ag.w - wr * hh.w;
            } else { a[0] = a[1] = a[2] = a[3] = 0.f; }
        } else if (MODE == 1) {
#pragma unroll
            for (int i = 0; i < 4; i++) {
                int kk = kb + k_l + i;
                float v = 0.f;
                if (rowok && kk < KIN)
                    v = (kk < AD) ? Vf[(size_t)sidx * AD + kk]
                                  : Eb[(size_t)grow * BD + (kk - AD)];
                a[i] = v;
            }
        } else { // MODE 3
#pragma unroll
            for (int i = 0; i < 4; i++) {
                int kk = kb + k_l + i;
                float v = 0.f;
                if (rowok && kk < KOUT)
                    v = (kk < AD) ? Vf[(size_t)grow * AD + kk]
                                  : agg[(size_t)grow * HID + (kk - AD)];
                a[i] = v;
            }
        }
        As[k_l + 0][row_l] = a[0];
        As[k_l + 1][row_l] = a[1];
        As[k_l + 2][row_l] = a[2];
        As[k_l + 3][row_l] = a[3];

        // ---- B tile: W[N,K] row-major, Bs[k][j] ----
#pragma unroll
        for (int i = 0; i < 4; i++) {
            int kk = kb + k_l + i;
            Bs[k_l + i][row_l] = (kk < K) ? W[(size_t)(jb + row_l) * K + kk] : 0.f;
        }
        __syncthreads();

#pragma unroll
        for (int k = 0; k < 8; k++) {
            float4 a0 = *(const float4*)&As[k][tm0];
            float4 a1 = *(const float4*)&As[k][tm0 + 4];
            float4 b0 = *(const float4*)&Bs[k][tn0];
            float4 b1 = *(const float4*)&Bs[k][tn0 + 4];
            float av[8] = {a0.x, a0.y, a0.z, a0.w, a1.x, a1.y, a1.z, a1.w};
            float bv[8] = {b0.x, b0.y, b0.z, b0.w, b1.x, b1.y, b1.z, b1.w};
#pragma unroll
            for (int i = 0; i < 8; i++)
#pragma unroll
                for (int j = 0; j < 8; j++)
                    acc[i][j] += av[i] * bv[j];
        }
        __syncthreads();
    }

    // ---- epilogue: add + relu, float4 stores ----
#pragma unroll
    for (int i = 0; i < 8; i++) {
        int gr = blockIdx.x * 128 + tm0 + i;
        if (gr >= M) break;
        size_t base = (size_t)gr * HID + jb + tn0;
#pragma unroll
        for (int j4 = 0; j4 < 2; j4++) {
            float4 v;
            v.x = acc[i][j4 * 4 + 0];
            v.y = acc[i][j4 * 4 + 1];
            v.z = acc[i][j4 * 4 + 2];
            v.w = acc[i][j4 * 4 + 3];
            if (MODE == 2) {
                float4 r = *(const float4*)(h0 + base + j4 * 4);
                v.x += r.x; v.y += r.y; v.z += r.z; v.w += r.w;
            }
            if (MODE == 3) {
                const float* bp = bias + jb + tn0 + j4 * 4;
                v.x += bp[0]; v.y += bp[1]; v.z += bp[2]; v.w += bp[3];
            }
            v.x = fmaxf(v.x, 0.f); v.y = fmaxf(v.y, 0.f);
            v.z = fmaxf(v.z, 0.f); v.w = fmaxf(v.w, 0.f);
            *(float4*)(C + base + j4 * 4) = v;
        }
    }
}

// ---------------- driver -----------------------------------------------------
extern "C" void kernel_launch(void* const* d_in, const int* in_sizes, int n_in,
                              void* d_out, int out_size)
{
    const float* V     = (const float*)d_in[0];
    const float* E     = (const float*)d_in[1];
    const int*   eidx  = (const int*)d_in[2];   // int32 (JAX default x64 disabled)
    const int*   rev   = (const int*)d_in[3];
    const int*   batch = (const int*)d_in[4];
    const float* wgt   = (const float*)d_in[5];
    const float* W_i   = (const float*)d_in[6];
    const float* W_h   = (const float*)d_in[7];
    const float* W_o   = (const float*)d_in[8];
    const float* b_o   = (const float*)d_in[9];

    const int* src = eidx;
    const int* dst = eidx + NEDGE;
    float* out = (float*)d_out;

    float *h0, *hA, *hB, *agg;
    cudaGetSymbolAddress((void**)&h0,  g_h0);
    cudaGetSymbolAddress((void**)&hA,  g_hA);
    cudaGetSymbolAddress((void**)&hB,  g_hB);
    cudaGetSymbolAddress((void**)&agg, g_agg);

    const dim3 blk(256);
    const dim3 grid_e((NEDGE + 127) / 128, 4);  // edge GEMMs
    const dim3 grid_a((NA    + 127) / 128, 4);  // atom GEMM
    const int  aggN4    = (NA * HID) / 4;
    const int  zeroGrid = (aggN4 + 255) / 256;
    const int  scatGrid = (NEDGE * 128 + 255) / 256;

    // 1) h0 = relu([V[src];E] @ W_i^T)
    gemm_k<1><<<grid_e, blk>>>(nullptr, W_i, V, E, src, nullptr, nullptr,
                               nullptr, nullptr, nullptr, h0, NEDGE, KIN);

    // 2) three message-passing steps (ping-pong h buffers)
    const float* hin = h0;
    float* houts[3] = { hA, hB, hA };
    for (int t = 0; t < 3; t++) {
        zero_k<<<zeroGrid, blk>>>((float4*)agg, aggN4);
        scatter_k<<<scatGrid, blk>>>(hin, dst, wgt, agg);
        gemm_k<2><<<grid_e, blk>>>(hin, W_h, nullptr, nullptr, src, rev, wgt,
                                   agg, h0, nullptr, houts[t], NEDGE, HID);
        hin = houts[t];
    }
    float* hFinal = hA;

    // 3) final aggregation (unweighted)
    zero_k<<<zeroGrid, blk>>>((float4*)agg, aggN4);
    scatter_k<<<scatGrid, blk>>>(hFinal, dst, nullptr, agg);

    // 4) h_atom = relu([V;agg] @ W_o^T + b_o) -> d_out[0 : 51.2M)
    gemm_k<3><<<grid_a, blk>>>(nullptr, W_o, V, nullptr, nullptr, nullptr,
                               nullptr, agg, nullptr, b_o, out, NA, KOUT);

    // 5) atom_batch as float -> d_out[51.2M : 51.3M)
    batch_k<<<(NA + 255) / 256, blk>>>(batch, out + (size_t)NA * HID);

    // 6) h -> d_out[51.3M : 153.7M)
    const int hN4 = (NEDGE * HID) / 4;
    copy4_k<<<(hN4 + 255) / 256, blk>>>((const float4*)hFinal,
                                        (float4*)(out + (size_t)NA * HID + NA), hN4);
}

// round 4
// speedup vs baseline: 1.1694x; 1.1694x over previous
#include <cuda_runtime.h>

#define NA    100000
#define NEDGE 200000
#define HID   512
#define AD    133
#define BD    14
#define KIN   147   // AD + BD
#define KOUT  645   // AD + HID

// ---------------- scratch (static device globals; no allocation) ------------
__device__ float g_h0 [(size_t)NEDGE * HID];
__device__ float g_hA [(size_t)NEDGE * HID];
__device__ float g_hB [(size_t)NEDGE * HID];
__device__ float g_agg[(size_t)NA    * HID];

// ---------------- utility kernels ------------------------------------------
__global__ void zero_k(float4* __restrict__ p, int n4) {
    int i = blockIdx.x * blockDim.x + threadIdx.x;
    if (i < n4) p[i] = make_float4(0.f, 0.f, 0.f, 0.f);
}

__global__ void scatter_k(const float* __restrict__ h,
                          const int* __restrict__ dst,
                          const float* __restrict__ wgt,
                          float* __restrict__ agg) {
    int idx = blockIdx.x * blockDim.x + threadIdx.x;      // NEDGE * 128 threads
    if (idx >= NEDGE * 128) return;
    int e = idx >> 7;
    int c = (idx & 127) << 2;
    int d = dst[e];
    float w = wgt ? wgt[e] : 1.0f;
    float4 hv = *(const float4*)(h + (size_t)e * HID + c);
    float* a = agg + (size_t)d * HID + c;
    atomicAdd(a + 0, w * hv.x);
    atomicAdd(a + 1, w * hv.y);
    atomicAdd(a + 2, w * hv.z);
    atomicAdd(a + 3, w * hv.w);
}

__global__ void batch_k(const int* __restrict__ b, float* __restrict__ out) {
    int i = blockIdx.x * blockDim.x + threadIdx.x;
    if (i < NA) out[i] = (float)b[i];
}

__global__ void copy4_k(const float4* __restrict__ src, float4* __restrict__ dst, int n4) {
    int i = blockIdx.x * blockDim.x + threadIdx.x;
    if (i < n4) dst[i] = src[i];
}

// ---------------- fused, double-buffered, prefetching SGEMM ------------------
// C[M,512] = relu( A @ W^T (+ add) )
// MODE 1: A row e = [V[src[e]] ; E[e]]                          K=147
// MODE 2: A row e = agg[src[e]] - wgt[rev[e]] * Hin[rev[e]]     K=512, add=h0[row]
// MODE 3: A row i = [V[i] ; agg[i]]                             K=645, add=bias[col]
template <int MODE>
__global__ __launch_bounds__(256, 2)
void gemm_k(const float* __restrict__ Hin,
            const float* __restrict__ W,
            const float* __restrict__ Vf,
            const float* __restrict__ Eb,
            const int* __restrict__ src,
            const int* __restrict__ rev,
            const float* __restrict__ wgt,
            const float* __restrict__ agg,
            const float* __restrict__ h0,
            const float* __restrict__ bias,
            float* __restrict__ C,
            int M, int K)
{
    __shared__ __align__(16) float As[2][8][132];
    __shared__ __align__(16) float Bs[2][8][132];

    const int tid   = threadIdx.x;
    const int row_l = tid >> 1;            // 0..127 (A row within tile, also B col)
    const int k_l   = (tid & 1) * 4;       // 0 or 4
    const int grow  = blockIdx.x * 128 + row_l;
    const int jb    = blockIdx.y * 128;
    const bool rowok = (grow < M);

    int   sidx = 0, ridx = 0;
    float wr   = 0.f;
    if (MODE == 1) { if (rowok) sidx = src[grow]; }
    if (MODE == 2) { if (rowok) { sidx = src[grow]; ridx = rev[grow]; wr = wgt[ridx]; } }

    const int tm0 = (tid >> 4) * 8;
    const int tn0 = (tid & 15) * 8;

    float acc[8][8];
#pragma unroll
    for (int i = 0; i < 8; i++)
#pragma unroll
        for (int j = 0; j < 8; j++) acc[i][j] = 0.f;

    // prefetch registers
    float4 agP, hhP, bP4;
    float  aP[4], bP[4];

#define GLOAD(kb) do {                                                          \
    if (MODE == 2) {                                                            \
        if (rowok) {                                                            \
            agP = *(const float4*)(agg + (size_t)sidx * HID + (kb) + k_l);      \
            hhP = *(const float4*)(Hin + (size_t)ridx * HID + (kb) + k_l);      \
        }                                                                       \
        bP4 = *(const float4*)(W + (size_t)(jb + row_l) * K + (kb) + k_l);      \
    } else {                                                                    \
        _Pragma("unroll")                                                       \
        for (int i = 0; i < 4; i++) {                                           \
            int kk = (kb) + k_l + i;                                            \
            float v = 0.f;                                                      \
            if (MODE == 1) {                                                    \
                if (rowok && kk < KIN)                                          \
                    v = (kk < AD) ? Vf[(size_t)sidx * AD + kk]                  \
                                  : Eb[(size_t)grow * BD + (kk - AD)];          \
            } else {                                                            \
                if (rowok && kk < KOUT)                                         \
                    v = (kk < AD) ? Vf[(size_t)grow * AD + kk]                  \
                                  : agg[(size_t)grow * HID + (kk - AD)];        \
            }                                                                   \
            aP[i] = v;                                                          \
        }                                                                       \
        _Pragma("unroll")                                                       \
        for (int i = 0; i < 4; i++) {                                           \
            int kk = (kb) + k_l + i;                                            \
            bP[i] = (kk < K) ? W[(size_t)(jb + row_l) * K + kk] : 0.f;          \
        }                                                                       \
    } } while (0)

#define SSTORE(buf) do {                                                        \
    if (MODE == 2) {                                                            \
        float a0, a1, a2, a3;                                                   \
        if (rowok) {                                                            \
            a0 = agP.x - wr * hhP.x;  a1 = agP.y - wr * hhP.y;                  \
            a2 = agP.z - wr * hhP.z;  a3 = agP.w - wr * hhP.w;                  \
        } else { a0 = a1 = a2 = a3 = 0.f; }                                     \
        As[buf][k_l + 0][row_l] = a0;  As[buf][k_l + 1][row_l] = a1;            \
        As[buf][k_l + 2][row_l] = a2;  As[buf][k_l + 3][row_l] = a3;            \
        Bs[buf][k_l + 0][row_l] = bP4.x;  Bs[buf][k_l + 1][row_l] = bP4.y;      \
        Bs[buf][k_l + 2][row_l] = bP4.z;  Bs[buf][k_l + 3][row_l] = bP4.w;      \
    } else {                                                                    \
        _Pragma("unroll")                                                       \
        for (int i = 0; i < 4; i++) {                                           \
            As[buf][k_l + i][row_l] = aP[i];                                    \
            Bs[buf][k_l + i][row_l] = bP[i];                                    \
        }                                                                       \
    } } while (0)

    // prologue: tile 0
    GLOAD(0);
    SSTORE(0);
    __syncthreads();

    const int nkb = (K + 7) >> 3;
    for (int t = 0; t < nkb; t++) {
        const int cur = t & 1;
        const bool nxt = (t + 1 < nkb);
        if (nxt) GLOAD((t + 1) * 8);    // global prefetch overlaps FMA below

#pragma unroll
        for (int k = 0; k < 8; k++) {
            float4 a0 = *(const float4*)&As[cur][k][tm0];
            float4 a1 = *(const float4*)&As[cur][k][tm0 + 4];
            float4 b0 = *(const float4*)&Bs[cur][k][tn0];
            float4 b1 = *(const float4*)&Bs[cur][k][tn0 + 4];
            float av[8] = {a0.x, a0.y, a0.z, a0.w, a1.x, a1.y, a1.z, a1.w};
            float bv[8] = {b0.x, b0.y, b0.z, b0.w, b1.x, b1.y, b1.z, b1.w};
#pragma unroll
            for (int i = 0; i < 8; i++)
#pragma unroll
                for (int j = 0; j < 8; j++)
                    acc[i][j] += av[i] * bv[j];
        }

        if (nxt) {
            SSTORE(1 - cur);
            __syncthreads();
        }
    }
#undef GLOAD
#undef SSTORE

    // ---- epilogue: add + relu, float4 stores ----
#pragma unroll
    for (int i = 0; i < 8; i++) {
        int gr = blockIdx.x * 128 + tm0 + i;
        if (gr >= M) break;
        size_t base = (size_t)gr * HID + jb + tn0;
#pragma unroll
        for (int j4 = 0; j4 < 2; j4++) {
            float4 v;
            v.x = acc[i][j4 * 4 + 0];
            v.y = acc[i][j4 * 4 + 1];
            v.z = acc[i][j4 * 4 + 2];
            v.w = acc[i][j4 * 4 + 3];
            if (MODE == 2) {
                float4 r = *(const float4*)(h0 + base + j4 * 4);
                v.x += r.x; v.y += r.y; v.z += r.z; v.w += r.w;
            }
            if (MODE == 3) {
                const float* bp = bias + jb + tn0 + j4 * 4;
                v.x += bp[0]; v.y += bp[1]; v.z += bp[2]; v.w += bp[3];
            }
            v.x = fmaxf(v.x, 0.f); v.y = fmaxf(v.y, 0.f);
            v.z = fmaxf(v.z, 0.f); v.w = fmaxf(v.w, 0.f);
            *(float4*)(C + base + j4 * 4) = v;
        }
    }
}

// ---------------- driver -----------------------------------------------------
extern "C" void kernel_launch(void* const* d_in, const int* in_sizes, int n_in,
                              void* d_out, int out_size)
{
    const float* V     = (const float*)d_in[0];
    const float* E     = (const float*)d_in[1];
    const int*   eidx  = (const int*)d_in[2];   // int32 (JAX default x64 disabled)
    const int*   rev   = (const int*)d_in[3];
    const int*   batch = (const int*)d_in[4];
    const float* wgt   = (const float*)d_in[5];
    const float* W_i   = (const float*)d_in[6];
    const float* W_h   = (const float*)d_in[7];
    const float* W_o   = (const float*)d_in[8];
    const float* b_o   = (const float*)d_in[9];

    const int* src = eidx;
    const int* dst = eidx + NEDGE;
    float* out = (float*)d_out;

    float *h0, *hA, *hB, *agg;
    cudaGetSymbolAddress((void**)&h0,  g_h0);
    cudaGetSymbolAddress((void**)&hA,  g_hA);
    cudaGetSymbolAddress((void**)&hB,  g_hB);
    cudaGetSymbolAddress((void**)&agg, g_agg);

    const dim3 blk(256);
    const dim3 grid_e((NEDGE + 127) / 128, 4);  // edge GEMMs
    const dim3 grid_a((NA    + 127) / 128, 4);  // atom GEMM
    const int  aggN4    = (NA * HID) / 4;
    const int  zeroGrid = (aggN4 + 255) / 256;
    const int  scatGrid = (NEDGE * 128 + 255) / 256;

    // 1) h0 = relu([V[src];E] @ W_i^T)
    gemm_k<1><<<grid_e, blk>>>(nullptr, W_i, V, E, src, nullptr, nullptr,
                               nullptr, nullptr, nullptr, h0, NEDGE, KIN);

    // 2) three message-passing steps (ping-pong h buffers)
    const float* hin = h0;
    float* houts[3] = { hA, hB, hA };
    for (int t = 0; t < 3; t++) {
        zero_k<<<zeroGrid, blk>>>((float4*)agg, aggN4);
        scatter_k<<<scatGrid, blk>>>(hin, dst, wgt, agg);
        gemm_k<2><<<grid_e, blk>>>(hin, W_h, nullptr, nullptr, src, rev, wgt,
                                   agg, h0, nullptr, houts[t], NEDGE, HID);
        hin = houts[t];
    }
    float* hFinal = hA;

    // 3) final aggregation (unweighted)
    zero_k<<<zeroGrid, blk>>>((float4*)agg, aggN4);
    scatter_k<<<scatGrid, blk>>>(hFinal, dst, nullptr, agg);

    // 4) h_atom = relu([V;agg] @ W_o^T + b_o) -> d_out[0 : 51.2M)
    gemm_k<3><<<grid_a, blk>>>(nullptr, W_o, V, nullptr, nullptr, nullptr,
                               nullptr, agg, nullptr, b_o, out, NA, KOUT);

    // 5) atom_batch as float -> d_out[51.2M : 51.3M)
    batch_k<<<(NA + 255) / 256, blk>>>(batch, out + (size_t)NA * HID);

    // 6) h -> d_out[51.3M : 153.7M)
    const int hN4 = (NEDGE * HID) / 4;
    copy4_k<<<(hN4 + 255) / 256, blk>>>((const float4*)hFinal,
                                        (float4*)(out + (size_t)NA * HID + NA), hN4);
}

// round 6
// speedup vs baseline: 2.1769x; 1.8616x over previous
#include <cuda_runtime.h>
#include <cstdint>

#define NA    100000
#define NEDGE 200000
#define HID   512
#define AD    133
#define BD    14
#define KIN   147   // AD + BD
#define KOUT  645   // AD + HID
#define KP1   160   // KIN padded to 32
#define KP2   512
#define KP3   672   // KOUT padded to 32
#define CK    32    // K chunk

// ---------------- scratch (static device globals; no allocation) ------------
__device__ float g_h0 [(size_t)NEDGE * HID];
__device__ float g_hA [(size_t)NEDGE * HID];
__device__ float g_hB [(size_t)NEDGE * HID];
__device__ float g_agg[(size_t)NA    * HID];
// pre-split weights (bf16 hi/lo), K-padded
__device__ __align__(16) unsigned short g_WiH[512 * KP1], g_WiL[512 * KP1];
__device__ __align__(16) unsigned short g_WhH[512 * KP2], g_WhL[512 * KP2];
__device__ __align__(16) unsigned short g_WoH[512 * KP3], g_WoL[512 * KP3];

// ---------------- helpers ----------------------------------------------------
__device__ __forceinline__ unsigned short f2bf(float x) {
    unsigned u = __float_as_uint(x);
    unsigned r = u + 0x7fffu + ((u >> 16) & 1u);   // RNE
    return (unsigned short)(r >> 16);
}
__device__ __forceinline__ float bf2f(unsigned short b) {
    return __uint_as_float(((unsigned)b) << 16);
}
__device__ __forceinline__ uint32_t smem_u32(const void* p) {
    uint32_t a;
    asm("{ .reg .u64 t; cvta.to.shared.u64 t, %1; cvt.u32.u64 %0, t; }" : "=r"(a) : "l"(p));
    return a;
}
__device__ __forceinline__ void ldsm4(uint32_t* r, uint32_t addr) {
    asm volatile("ldmatrix.sync.aligned.m8n8.x4.shared.b16 {%0,%1,%2,%3}, [%4];"
                 : "=r"(r[0]), "=r"(r[1]), "=r"(r[2]), "=r"(r[3]) : "r"(addr));
}
__device__ __forceinline__ void mma16816(float* d, const uint32_t* a,
                                         uint32_t b0, uint32_t b1) {
    asm volatile(
        "mma.sync.aligned.m16n8k16.row.col.f32.bf16.bf16.f32 "
        "{%0,%1,%2,%3}, {%4,%5,%6,%7}, {%8,%9}, {%0,%1,%2,%3};"
        : "+f"(d[0]), "+f"(d[1]), "+f"(d[2]), "+f"(d[3])
        : "r"(a[0]), "r"(a[1]), "r"(a[2]), "r"(a[3]), "r"(b0), "r"(b1));
}
// split 8 fp32 -> hi/lo bf16 packed (uint4 each = 8 bf16)
__device__ __forceinline__ void split8(const float* x, uint4& hi, uint4& lo) {
    unsigned hb[8], lb[8];
#pragma unroll
    for (int i = 0; i < 8; i++) {
        hb[i] = f2bf(x[i]);
        lb[i] = f2bf(x[i] - bf2f((unsigned short)hb[i]));
    }
    hi.x = hb[0] | (hb[1] << 16); hi.y = hb[2] | (hb[3] << 16);
    hi.z = hb[4] | (hb[5] << 16); hi.w = hb[6] | (hb[7] << 16);
    lo.x = lb[0] | (lb[1] << 16); lo.y = lb[2] | (lb[3] << 16);
    lo.z = lb[4] | (lb[5] << 16); lo.w = lb[6] | (lb[7] << 16);
}

// ---------------- utility kernels ------------------------------------------
__global__ void splitw_k(const float* __restrict__ W,
                         unsigned short* __restrict__ hi,
                         unsigned short* __restrict__ lo,
                         int N, int K, int Kp) {
    int idx = blockIdx.x * blockDim.x + threadIdx.x;
    if (idx >= N * Kp) return;
    int n = idx / Kp, k = idx - n * Kp;
    float v = (k < K) ? W[(size_t)n * K + k] : 0.f;
    unsigned short h = f2bf(v);
    hi[idx] = h;
    lo[idx] = f2bf(v - bf2f(h));
}

__global__ void zero_k(float4* __restrict__ p, int n4) {
    int i = blockIdx.x * blockDim.x + threadIdx.x;
    if (i < n4) p[i] = make_float4(0.f, 0.f, 0.f, 0.f);
}

__global__ void scatter_k(const float* __restrict__ h,
                          const int* __restrict__ dst,
                          const float* __restrict__ wgt,
                          float* __restrict__ agg) {
    int idx = blockIdx.x * blockDim.x + threadIdx.x;
    if (idx >= NEDGE * 128) return;
    int e = idx >> 7;
    int c = (idx & 127) << 2;
    int d = dst[e];
    float w = wgt ? wgt[e] : 1.0f;
    float4 hv = *(const float4*)(h + (size_t)e * HID + c);
    float* a = agg + (size_t)d * HID + c;
    atomicAdd(a + 0, w * hv.x);
    atomicAdd(a + 1, w * hv.y);
    atomicAdd(a + 2, w * hv.z);
    atomicAdd(a + 3, w * hv.w);
}

__global__ void batch_k(const int* __restrict__ b, float* __restrict__ out) {
    int i = blockIdx.x * blockDim.x + threadIdx.x;
    if (i < NA) out[i] = (float)b[i];
}

__global__ void copy4_k(const float4* __restrict__ src, float4* __restrict__ dst, int n4) {
    int i = blockIdx.x * blockDim.x + threadIdx.x;
    if (i < n4) dst[i] = src[i];
}

// ---------------- tensor-core (mma.sync) split-bf16 GEMM ---------------------
// C[M,512] = relu( A @ W^T (+ add) ).  CTA tile 128(M) x 128(N), K chunks of 32.
// MODE 1: A row e = [V[src[e]] ; E[e]]                          K=147
// MODE 2: A row e = agg[src[e]] - wgt[rev[e]] * Hin[rev[e]]     K=512, add=h0[row]
// MODE 3: A row i = [V[i] ; agg[i]]                             K=645, add=bias[col]
// smem per buffer: A 128x128B (hi|lo interleaved per row) + B same = 32KB; x2 = 64KB
#define SMEM_GEMM 65536

template <int MODE>
__global__ __launch_bounds__(512, 1)
void gemm_mma(const float* __restrict__ Hin,
              const unsigned short* __restrict__ WH,
              const unsigned short* __restrict__ WL,
              const float* __restrict__ Vf,
              const float* __restrict__ Eb,
              const int* __restrict__ src,
              const int* __restrict__ rev,
              const float* __restrict__ wgt,
              const float* __restrict__ agg,
              const float* __restrict__ h0,
              const float* __restrict__ bias,
              float* __restrict__ C,
              int M, int K, int Kp)
{
    extern __shared__ __align__(1024) char sm[];
    const uint32_t sb = smem_u32(sm);
    const int tid   = threadIdx.x;
    const int lane  = tid & 31;
    const int warp  = tid >> 5;
    const int warpM = warp >> 2;        // 0..3  (32 rows each)
    const int warpN = warp & 3;         // 0..3  (32 cols each)

    const int jb = blockIdx.x * 128;    // N block (fastest -> L2 reuse of A)
    const int mb = blockIdx.y * 128;    // M block

    // loader mapping: 4 threads per row, each covers 8 k-values (16B unit)
    const int arow  = tid >> 2;         // 0..127
    const int aq    = tid & 3;
    const int agrow = mb + arow;
    const bool aok  = (agrow < M);

    int sidx = 0, ridx = 0; float wr = 0.f;
    if (MODE == 1) { if (aok) sidx = src[agrow]; }
    if (MODE == 2) { if (aok) { sidx = src[agrow]; ridx = rev[agrow]; wr = wgt[ridx]; } }

    float acc[2][4][4];
#pragma unroll
    for (int i = 0; i < 2; i++)
#pragma unroll
        for (int n = 0; n < 4; n++)
#pragma unroll
            for (int k = 0; k < 4; k++) acc[i][n][k] = 0.f;

    // prefetch registers
    float4 ag0, ag1, hh0, hh1;
    float  ar[8];
    uint4  bhi, blo;

#define GLOAD(kb) do {                                                          \
    if (MODE == 2) {                                                            \
        if (aok) {                                                              \
            const float* ap = agg + (size_t)sidx * HID + (kb) + aq * 8;         \
            const float* hp = Hin + (size_t)ridx * HID + (kb) + aq * 8;         \
            ag0 = *(const float4*)ap;  ag1 = *(const float4*)(ap + 4);          \
            hh0 = *(const float4*)hp;  hh1 = *(const float4*)(hp + 4);          \
        }                                                                       \
    } else {                                                                    \
        _Pragma("unroll")                                                       \
        for (int i = 0; i < 8; i++) {                                           \
            int kk = (kb) + aq * 8 + i; float v = 0.f;                          \
            if (MODE == 1) {                                                    \
                if (aok && kk < KIN)                                            \
                    v = (kk < AD) ? Vf[(size_t)sidx * AD + kk]                  \
                                  : Eb[(size_t)agrow * BD + (kk - AD)];         \
            } else {                                                            \
                if (aok && kk < KOUT)                                           \
                    v = (kk < AD) ? Vf[(size_t)agrow * AD + kk]                 \
                                  : agg[(size_t)agrow * HID + (kk - AD)];       \
            }                                                                   \
            ar[i] = v;                                                          \
        }                                                                       \
    }                                                                           \
    bhi = *(const uint4*)(WH + (size_t)(jb + arow) * Kp + (kb) + aq * 8);       \
    blo = *(const uint4*)(WL + (size_t)(jb + arow) * Kp + (kb) + aq * 8);       \
} while (0)

#define SW(o) ((o) ^ (((o) >> 3) & 0x70))

#define SSTORE(base) do {                                                       \
    float x[8];                                                                 \
    if (MODE == 2) {                                                            \
        if (aok) {                                                              \
            x[0]=ag0.x-wr*hh0.x; x[1]=ag0.y-wr*hh0.y;                           \
            x[2]=ag0.z-wr*hh0.z; x[3]=ag0.w-wr*hh0.w;                           \
            x[4]=ag1.x-wr*hh1.x; x[5]=ag1.y-wr*hh1.y;                           \
            x[6]=ag1.z-wr*hh1.z; x[7]=ag1.w-wr*hh1.w;                           \
        } else { _Pragma("unroll") for (int i = 0; i < 8; i++) x[i] = 0.f; }    \
    } else { _Pragma("unroll") for (int i = 0; i < 8; i++) x[i] = ar[i]; }      \
    uint4 hi, lo; split8(x, hi, lo);                                            \
    int oa = arow * 128 + aq * 16;                                              \
    *(uint4*)(sm + (base) + SW(oa)) = hi;                                       \
    int oa2 = oa + 64;                                                          \
    *(uint4*)(sm + (base) + SW(oa2)) = lo;                                      \
    *(uint4*)(sm + (base) + 16384 + SW(oa))  = bhi;                             \
    *(uint4*)(sm + (base) + 16384 + SW(oa2)) = blo;                             \
} while (0)

#define DOMMA(base) do {                                                        \
    _Pragma("unroll")                                                           \
    for (int s = 0; s < 2; s++) {                                               \
        uint32_t Ah[2][4], Al[2][4], Bh[2][4], Bl[2][4];                        \
        const int cb = s * 32 + ((lane >> 4) << 4);                             \
        _Pragma("unroll")                                                       \
        for (int i = 0; i < 2; i++) {                                           \
            int r = warpM * 32 + i * 16 + (lane & 15);                          \
            int o = r * 128 + cb;                                               \
            ldsm4(Ah[i], sb + (base) + SW(o));                                  \
            int o2 = o + 64;                                                    \
            ldsm4(Al[i], sb + (base) + SW(o2));                                 \
        }                                                                       \
        _Pragma("unroll")                                                       \
        for (int j = 0; j < 2; j++) {                                           \
            int r = warpN * 32 + j * 16 + (lane & 15);                          \
            int o = r * 128 + cb;                                               \
            ldsm4(Bh[j], sb + (base) + 16384 + SW(o));                          \
            int o2 = o + 64;                                                    \
            ldsm4(Bl[j], sb + (base) + 16384 + SW(o2));                         \
        }                                                                       \
        _Pragma("unroll")                                                       \
        for (int i = 0; i < 2; i++)                                             \
            _Pragma("unroll")                                                   \
            for (int nt = 0; nt < 4; nt++) {                                    \
                int j = nt >> 1, sel = nt & 1;                                  \
                mma16816(acc[i][nt], Ah[i], Bh[j][sel], Bh[j][sel + 2]);        \
                mma16816(acc[i][nt], Al[i], Bh[j][sel], Bh[j][sel + 2]);        \
                mma16816(acc[i][nt], Ah[i], Bl[j][sel], Bl[j][sel + 2]);        \
            }                                                                   \
    }                                                                           \
} while (0)

    const int nc = (K + CK - 1) / CK;
    GLOAD(0);
    for (int t = 0; t < nc; t++) {
        const int base = (t & 1) * 32768;
        SSTORE(base);
        __syncthreads();
        if (t + 1 < nc) GLOAD((t + 1) * CK);
        DOMMA(base);
    }
#undef GLOAD
#undef SSTORE
#undef DOMMA
#undef SW

    // ---- epilogue: acc -> (+h0/bias) -> relu -> C --------------------------
#pragma unroll
    for (int i = 0; i < 2; i++)
#pragma unroll
        for (int nt = 0; nt < 4; nt++) {
            const int r0 = mb + warpM * 32 + i * 16 + (lane >> 2);
            const int c  = jb + warpN * 32 + nt * 8 + (lane & 3) * 2;
#pragma unroll
            for (int hh = 0; hh < 2; hh++) {
                const int r = r0 + hh * 8;
                if (r < M) {
                    float v0 = acc[i][nt][hh * 2 + 0];
                    float v1 = acc[i][nt][hh * 2 + 1];
                    const size_t base = (size_t)r * HID + c;
                    if (MODE == 2) {
                        float2 a = *(const float2*)(h0 + base);
                        v0 += a.x; v1 += a.y;
                    }
                    if (MODE == 3) { v0 += bias[c]; v1 += bias[c + 1]; }
                    float2 o;
                    o.x = fmaxf(v0, 0.f);
                    o.y = fmaxf(v1, 0.f);
                    *(float2*)(C + base) = o;
                }
            }
        }
}

// ---------------- driver -----------------------------------------------------
extern "C" void kernel_launch(void* const* d_in, const int* in_sizes, int n_in,
                              void* d_out, int out_size)
{
    const float* V     = (const float*)d_in[0];
    const float* E     = (const float*)d_in[1];
    const int*   eidx  = (const int*)d_in[2];
    const int*   rev   = (const int*)d_in[3];
    const int*   batch = (const int*)d_in[4];
    const float* wgt   = (const float*)d_in[5];
    const float* W_i   = (const float*)d_in[6];
    const float* W_h   = (const float*)d_in[7];
    const float* W_o   = (const float*)d_in[8];
    const float* b_o   = (const float*)d_in[9];

    const int* src = eidx;
    const int* dst = eidx + NEDGE;
    float* out = (float*)d_out;

    float *h0, *hA, *hB, *agg;
    cudaGetSymbolAddress((void**)&h0,  g_h0);
    cudaGetSymbolAddress((void**)&hA,  g_hA);
    cudaGetSymbolAddress((void**)&hB,  g_hB);
    cudaGetSymbolAddress((void**)&agg, g_agg);
    unsigned short *WiH, *WiL, *WhH, *WhL, *WoH, *WoL;
    cudaGetSymbolAddress((void**)&WiH, g_WiH);
    cudaGetSymbolAddress((void**)&WiL, g_WiL);
    cudaGetSymbolAddress((void**)&WhH, g_WhH);
    cudaGetSymbolAddress((void**)&WhL, g_WhL);
    cudaGetSymbolAddress((void**)&WoH, g_WoH);
    cudaGetSymbolAddress((void**)&WoL, g_WoL);

    cudaFuncSetAttribute(gemm_mma<1>, cudaFuncAttributeMaxDynamicSharedMemorySize, SMEM_GEMM);
    cudaFuncSetAttribute(gemm_mma<2>, cudaFuncAttributeMaxDynamicSharedMemorySize, SMEM_GEMM);
    cudaFuncSetAttribute(gemm_mma<3>, cudaFuncAttributeMaxDynamicSharedMemorySize, SMEM_GEMM);

    const dim3 blk(512);
    const dim3 grid_e(4, (NEDGE + 127) / 128);   // N-fastest for A reuse in L2
    const dim3 grid_a(4, (NA    + 127) / 128);
    const int  aggN4    = (NA * HID) / 4;
    const int  zeroGrid = (aggN4 + 255) / 256;
    const int  scatGrid = (NEDGE * 128 + 255) / 256;

    // 0) pre-split weights to bf16 hi/lo (K-padded)
    splitw_k<<<(512 * KP1 + 255) / 256, 256>>>(W_i, WiH, WiL, 512, KIN,  KP1);
    splitw_k<<<(512 * KP2 + 255) / 256, 256>>>(W_h, WhH, WhL, 512, HID,  KP2);
    splitw_k<<<(512 * KP3 + 255) / 256, 256>>>(W_o, WoH, WoL, 512, KOUT, KP3);

    // 1) h0 = relu([V[src];E] @ W_i^T)
    gemm_mma<1><<<grid_e, blk, SMEM_GEMM>>>(nullptr, WiH, WiL, V, E, src, nullptr,
                                            nullptr, nullptr, nullptr, nullptr,
                                            h0, NEDGE, KIN, KP1);

    // 2) three message-passing steps (ping-pong h buffers)
    const float* hin = h0;
    float* houts[3] = { hA, hB, hA };
    for (int t = 0; t < 3; t++) {
        zero_k<<<zeroGrid, 256>>>((float4*)agg, aggN4);
        scatter_k<<<scatGrid, 256>>>(hin, dst, wgt, agg);
        gemm_mma<2><<<grid_e, blk, SMEM_GEMM>>>(hin, WhH, WhL, nullptr, nullptr,
                                                src, rev, wgt, agg, h0, nullptr,
                                                houts[t], NEDGE, HID, KP2);
        hin = houts[t];
    }
    float* hFinal = hA;

    // 3) final aggregation (unweighted)
    zero_k<<<zeroGrid, 256>>>((float4*)agg, aggN4);
    scatter_k<<<scatGrid, 256>>>(hFinal, dst, nullptr, agg);

    // 4) h_atom = relu([V;agg] @ W_o^T + b_o) -> d_out[0 : 51.2M)
    gemm_mma<3><<<grid_a, blk, SMEM_GEMM>>>(nullptr, WoH, WoL, V, nullptr,
                                            nullptr, nullptr, nullptr, agg,
                                            nullptr, b_o, out, NA, KOUT, KP3);

    // 5) atom_batch as float -> d_out[51.2M : 51.3M)
    batch_k<<<(NA + 255) / 256, 256>>>(batch, out + (size_t)NA * HID);

    // 6) h -> d_out[51.3M : 153.7M)
    const int hN4 = (NEDGE * HID) / 4;
    copy4_k<<<(hN4 + 255) / 256, 256>>>((const float4*)hFinal,
                                        (float4*)(out + (size_t)NA * HID + NA), hN4);
}